// round 15
// baseline (speedup 1.0000x reference)
#include <cuda_runtime.h>
#include <math_constants.h>
#include <cstdint>

// DifferentialAttention via warp-level mma.sync, fp16, software-pipelined across k-tiles:
// iter kt does softmax(kt) -> [QK(kt+1) || PV(kt)] so the tensor pipe stays fed through
// the softmax ALU stretch. K/V independently double-buffered. Row sums via ones-mma.
// Output assembled with red.global.add (attn1 adds A1/l, attn2 adds -exp(lam)*A2/l) onto
// a zeroed d_out -- no combine kernel, no scratch round-trip.
// B=2, H=12, S=2048, D=128, fp32 in/out.

#define SEQ  2048
#define Dh   128
#define BM   128
#define BN   64
#define NT   256
#define BHN  24
#define NQT  16
// (1/sqrt(128)) * log2(e): scores come out of QK in log2 units (scale carried by Q)
#define QSCALE_LOG2E 0.12751724f

// SMEM: 256B rows (128 f16), XOR-swizzled 16B chunks
#define O_QH  0
#define O_K0  32768
#define O_K1  49152
#define O_V0  65536
#define O_V1  81920
#define SM_TOTAL 98304

#define NOUT (2 * 12 * 2048 * 128)

static __device__ __forceinline__ uint32_t pk2h(float x, float y) {   // f16x2: low=x, high=y
    uint32_t r;
    asm("cvt.rn.f16x2.f32 %0, %1, %2;" : "=r"(r) : "f"(y), "f"(x));
    return r;
}
static __device__ __forceinline__ uint32_t ex2h2(uint32_t a) {        // 2^x on both f16 halves
    uint32_t r;
    asm("ex2.approx.f16x2 %0, %1;" : "=r"(r) : "r"(a));
    return r;
}
static __device__ __forceinline__ uint32_t s2u(const void* p) {
    uint32_t a;
    asm("{ .reg .u64 t; cvta.to.shared.u64 t, %1; cvt.u32.u64 %0, t; }" : "=r"(a) : "l"(p));
    return a;
}
static __device__ __forceinline__ void ldsm4(uint32_t addr, uint32_t r[4]) {
    asm volatile("ldmatrix.sync.aligned.m8n8.x4.shared.b16 {%0,%1,%2,%3}, [%4];"
                 : "=r"(r[0]), "=r"(r[1]), "=r"(r[2]), "=r"(r[3]) : "r"(addr));
}
static __device__ __forceinline__ void ldsm4t(uint32_t addr, uint32_t r[4]) {
    asm volatile("ldmatrix.sync.aligned.m8n8.x4.trans.shared.b16 {%0,%1,%2,%3}, [%4];"
                 : "=r"(r[0]), "=r"(r[1]), "=r"(r[2]), "=r"(r[3]) : "r"(addr));
}
static __device__ __forceinline__ void mma16816(float d[4], const uint32_t a[4],
                                                uint32_t b0, uint32_t b1) {
    asm volatile("mma.sync.aligned.m16n8k16.row.col.f32.f16.f16.f32 "
                 "{%0,%1,%2,%3}, {%4,%5,%6,%7}, {%8,%9}, {%0,%1,%2,%3};"
                 : "+f"(d[0]), "+f"(d[1]), "+f"(d[2]), "+f"(d[3])
                 : "r"(a[0]), "r"(a[1]), "r"(a[2]), "r"(a[3]), "r"(b0), "r"(b1));
}
static __device__ __forceinline__ void redadd(float* p, float v) {
    asm volatile("red.global.add.f32 [%0], %1;" :: "l"(p), "f"(v) : "memory");
}

// fill one 64x128 f16 K tile (4 rows x 16B per thread)
static __device__ __forceinline__ void fill_k(char* smc, const float* gk, size_t base,
                                              int tile, uint32_t koff, int frow, int fch) {
    size_t goff = base + (size_t)(tile * BN + frow * 4) * Dh + fch * 8;
    #pragma unroll
    for (int rr = 0; rr < 4; ++rr) {
        const float4* pk = (const float4*)(gk + goff + (size_t)rr * Dh);
        float4 f0 = pk[0], f1 = pk[1];
        int row = frow * 4 + rr;
        uint32_t sa = (uint32_t)((row * 256) + ((fch ^ (row & 7)) << 4));
        *(uint4*)(smc + koff + sa) = make_uint4(pk2h(f0.x, f0.y), pk2h(f0.z, f0.w),
                                                pk2h(f1.x, f1.y), pk2h(f1.z, f1.w));
    }
}
static __device__ __forceinline__ void fill_v(char* smc, const float* gv, size_t base,
                                              int tile, uint32_t voff, int frow, int fch) {
    size_t goff = base + (size_t)(tile * BN + frow * 4) * Dh + fch * 8;
    #pragma unroll
    for (int rr = 0; rr < 4; ++rr) {
        const float4* pv = (const float4*)(gv + goff + (size_t)rr * Dh);
        float4 v0 = pv[0], v1 = pv[1];
        int row = frow * 4 + rr;
        uint32_t sa = (uint32_t)((row * 256) + ((fch ^ (row & 7)) << 4));
        *(uint4*)(smc + voff + sa) = make_uint4(pk2h(v0.x, v0.y), pk2h(v0.z, v0.w),
                                                pk2h(v1.x, v1.y), pk2h(v1.z, v1.w));
    }
}

__global__ __launch_bounds__(NT, 2)
void diffattn_pl(const float* __restrict__ gq1, const float* __restrict__ gk1,
                 const float* __restrict__ gv,  const float* __restrict__ gq2,
                 const float* __restrict__ gk2, const float* __restrict__ glam,
                 float* __restrict__ gout)
{
    extern __shared__ __align__(1024) char smc[];
    const uint32_t sb = s2u(smc);
    const int t = threadIdx.x, wid = t >> 5, lane = t & 31;

    const int idx = blockIdx.x;
    const int a   = idx & 1;                  // 0: attn1, 1: attn2
    const int rst = idx >> 1;
    const int qt  = (NQT - 1) - (rst / BHN);  // heavy Q-tiles first
    const int bh  = rst % BHN;
    const int q0  = qt * BM;
    const size_t base = (size_t)bh * (size_t)(SEQ * Dh);
    const int nkt = 2 * qt + 2;

    const float* gq = a ? gq2 : gq1;
    const float* gk = a ? gk2 : gk1;

    const int rb = wid * 16;                  // warp's 16 Q rows

    // per-lane ldmatrix constants
    const int lr = lane & 7;
    const int lA = lr + ((lane >> 3) & 1) * 8;
    const int hA = (lane >> 4) & 1;
    const int cB = lane >> 3;

    const int frow = t >> 4, fch = t & 15;

    // ---- load Q (f16, pre-scaled by 1/sqrt(d)*log2e) ----
    #pragma unroll 2
    for (int it = 0; it < 8; ++it) {
        int fl = it * NT + t;
        int row = fl >> 4, ch = fl & 15;
        const float4* p = (const float4*)(gq + base + (size_t)(q0 + row) * Dh + ch * 8);
        float4 f0 = p[0], f1 = p[1];
        f0.x *= QSCALE_LOG2E; f0.y *= QSCALE_LOG2E; f0.z *= QSCALE_LOG2E; f0.w *= QSCALE_LOG2E;
        f1.x *= QSCALE_LOG2E; f1.y *= QSCALE_LOG2E; f1.z *= QSCALE_LOG2E; f1.w *= QSCALE_LOG2E;
        uint32_t sa = (uint32_t)(row * 256 + ((ch ^ (row & 7)) << 4));
        *(uint4*)(smc + O_QH + sa) = make_uint4(pk2h(f0.x, f0.y), pk2h(f0.z, f0.w),
                                                pk2h(f1.x, f1.y), pk2h(f1.z, f1.w));
    }

    // ---- prologue fills: K(0)->Kb0, V(0)->Vb0, K(1)->Kb1 ----
    fill_k(smc, gk, base, 0, O_K0, frow, fch);
    fill_v(smc, gv, base, 0, O_V0, frow, fch);
    fill_k(smc, gk, base, 1, O_K1, frow, fch);

    float o[16][4];
    #pragma unroll
    for (int nt = 0; nt < 16; ++nt)
        #pragma unroll
        for (int c = 0; c < 4; ++c) o[nt][c] = 0.0f;
    float l4[4] = {0.0f, 0.0f, 0.0f, 0.0f};
    float mb = 0.0f;
    float s[8][4];

    const uint32_t aRowH = sb + O_QH + (uint32_t)((rb + lA) * 256);
    const uint32_t ONE2 = 0x3C003C00u;
    const int rw0 = q0 + rb + (lane >> 2);

    __syncthreads();

    // ---- prologue QK(0) from Kb0 ----
    #pragma unroll
    for (int nt = 0; nt < 8; ++nt)
        #pragma unroll
        for (int c = 0; c < 4; ++c) s[nt][c] = 0.0f;
    #pragma unroll
    for (int kc2 = 0; kc2 < 4; ++kc2) {
        uint32_t ah[2][4];
        #pragma unroll
        for (int sc = 0; sc < 2; ++sc)
            ldsm4(aRowH + (uint32_t)(((2 * (2 * kc2 + sc) + hA) ^ lr) << 4), ah[sc]);
        uint32_t kb = sb + O_K0 + (uint32_t)(lr * 256) +
                      (uint32_t)((((4 * kc2 + cB) ^ lr) << 4));
        #pragma unroll
        for (int nt = 0; nt < 8; ++nt) {
            uint32_t b[4];
            ldsm4(kb + (uint32_t)(nt * 2048), b);
            mma16816(s[nt], ah[0], b[0], b[1]);
            mma16816(s[nt], ah[1], b[2], b[3]);
        }
    }
    __syncthreads();   // all warps done reading Kb0 before iter0 refills it

    for (int kt = 0; kt < nkt; ++kt) {
        const uint32_t kNext = ((kt + 1) & 1) ? O_K1 : O_K0;
        const uint32_t vCur  = (kt & 1) ? O_V1 : O_V0;

        // ---- causal mask on s(kt) (diagonal 128-block only) ----
        if (kt >= 2 * qt) {
            const int colb = kt * 64 + ((lane & 3) << 1);
            #pragma unroll
            for (int nt = 0; nt < 8; ++nt)
                #pragma unroll
                for (int c = 0; c < 4; ++c) {
                    int col = colb + nt * 8 + (c & 1);
                    int rw  = rw0 + 8 * (c >> 1);
                    if (col > rw) s[nt][c] = -CUDART_INF_F;
                }
        }

        // ---- per-warp softmax base from tile 0 ----
        if (kt == 0) {
            float m = -CUDART_INF_F;
            #pragma unroll
            for (int nt = 0; nt < 8; ++nt)
                #pragma unroll
                for (int c = 0; c < 4; ++c) m = fmaxf(m, s[nt][c]);
            #pragma unroll
            for (int d = 1; d < 32; d <<= 1)
                m = fmaxf(m, __shfl_xor_sync(0xffffffffu, m, d));
            mb = m;
        }

        // ---- softmax: s(kt) -> ph (frees s for QK(kt+1)) ----
        uint32_t ph[4][4];
        #pragma unroll
        for (int nt = 0; nt < 8; ++nt) {
            ph[nt >> 1][((nt & 1) << 1)]     = ex2h2(pk2h(s[nt][0] - mb, s[nt][1] - mb));
            ph[nt >> 1][((nt & 1) << 1) + 1] = ex2h2(pk2h(s[nt][2] - mb, s[nt][3] - mb));
        }

        // ---- fills for the future (write buffers idle this iter) ----
        if (kt + 2 < nkt) fill_k(smc, gk, base, kt + 2, (kt & 1) ? O_K1 : O_K0, frow, fch);
        if (kt + 1 < nkt) fill_v(smc, gv, base, kt + 1, ((kt + 1) & 1) ? O_V1 : O_V0, frow, fch);

        // ---- interleaved: QK(kt+1) into s  ||  l-mma + PV(kt) from ph ----
        const bool doQK = (kt + 1 < nkt);
        if (doQK) {
            #pragma unroll
            for (int nt = 0; nt < 8; ++nt)
                #pragma unroll
                for (int c = 0; c < 4; ++c) s[nt][c] = 0.0f;
        }
        #pragma unroll
        for (int kc = 0; kc < 4; ++kc) {
            if (doQK) {
                uint32_t ah[2][4];
                #pragma unroll
                for (int sc = 0; sc < 2; ++sc)
                    ldsm4(aRowH + (uint32_t)(((2 * (2 * kc + sc) + hA) ^ lr) << 4), ah[sc]);
                uint32_t kb = sb + kNext + (uint32_t)(lr * 256) +
                              (uint32_t)((((4 * kc + cB) ^ lr) << 4));
                #pragma unroll
                for (int nt = 0; nt < 8; ++nt) {
                    uint32_t b[4];
                    ldsm4(kb + (uint32_t)(nt * 2048), b);
                    mma16816(s[nt], ah[0], b[0], b[1]);
                    mma16816(s[nt], ah[1], b[2], b[3]);
                }
            }
            mma16816(l4, ph[kc], ONE2, ONE2);
            uint32_t vrow = sb + vCur + (uint32_t)((16 * kc + lA) * 256);
            #pragma unroll
            for (int nt2 = 0; nt2 < 8; ++nt2) {
                uint32_t b[4];
                ldsm4t(vrow + (uint32_t)((((2 * nt2 + hA) ^ lr) << 4)), b);
                mma16816(o[2 * nt2],     ph[kc], b[0], b[1]);
                mma16816(o[2 * nt2 + 1], ph[kc], b[2], b[3]);
            }
        }

        __syncthreads();   // fills visible; read buffers free for next iter's fills
    }

    // ---- epilogue: red.add into zeroed gout (attn1: +A1/l, attn2: -exp(lam)*A2/l) ----
    {
        const float sc = a ? -__expf(glam[0]) : 1.0f;
        const float i0 = sc / l4[0];   // row rw0
        const float i1 = sc / l4[2];   // row rw0+8
        #pragma unroll
        for (int nt = 0; nt < 16; ++nt) {
            const int d0 = nt * 8 + ((lane & 3) << 1);
            float* p0 = gout + base + (size_t)rw0 * Dh + d0;
            float* p1 = gout + base + (size_t)(rw0 + 8) * Dh + d0;
            redadd(p0,     o[nt][0] * i0);
            redadd(p0 + 1, o[nt][1] * i0);
            redadd(p1,     o[nt][2] * i1);
            redadd(p1 + 1, o[nt][3] * i1);
        }
    }
}

extern "C" void kernel_launch(void* const* d_in, const int* in_sizes, int n_in,
                              void* d_out, int out_size)
{
    (void)in_sizes; (void)n_in; (void)out_size;
    const float* q1  = (const float*)d_in[0];
    const float* k1  = (const float*)d_in[1];
    const float* v   = (const float*)d_in[2];
    const float* q2  = (const float*)d_in[3];
    const float* k2  = (const float*)d_in[4];
    const float* lam = (const float*)d_in[5];

    cudaMemsetAsync(d_out, 0, (size_t)NOUT * sizeof(float));
    cudaFuncSetAttribute(diffattn_pl, cudaFuncAttributeMaxDynamicSharedMemorySize, SM_TOTAL);
    diffattn_pl<<<2 * NQT * BHN, NT, SM_TOTAL>>>(q1, k1, v, q2, k2, lam, (float*)d_out);
}

// round 16
// speedup vs baseline: 1.1344x; 1.1344x over previous
#include <cuda_runtime.h>
#include <math_constants.h>
#include <cstdint>

// DifferentialAttention via warp-level mma.sync, fp16 1+1 pass, double-buffered K/V.
// Softmax via ex2.approx.f16x2 (scores in log2 units), row sums l via ones-mma.
// attn1 -> d_out (f32), attn2 -> lam*A2 staged as f16x2 in g_a2h; combine subtracts.
// B=2, H=12, S=2048, D=128, fp32 in/out.

#define SEQ  2048
#define Dh   128
#define BM   128
#define BN   64
#define NT   256
#define BHN  24
#define NQT  16
// (1/sqrt(128)) * log2(e): scores come out of QK in log2 units (scale carried by Q)
#define QSCALE_LOG2E 0.12751724f

// SMEM: 256B rows (128 f16), XOR-swizzled 16B chunks
#define O_QH  0
#define O_K0  32768
#define O_K1  49152
#define O_V0  65536
#define O_V1  81920
#define SM_TOTAL 98304

#define NOUT (2 * 12 * 2048 * 128)
__device__ uint32_t g_a2h[NOUT / 2];   // f16x2-packed lam*A2/l

static __device__ __forceinline__ uint32_t pk2h(float x, float y) {   // f16x2: low=x, high=y
    uint32_t r;
    asm("cvt.rn.f16x2.f32 %0, %1, %2;" : "=r"(r) : "f"(y), "f"(x));
    return r;
}
static __device__ __forceinline__ float2 up2h(uint32_t h) {
    float2 f;
    asm("{ .reg .b16 l, hh; mov.b32 {l, hh}, %2; cvt.f32.f16 %0, l; cvt.f32.f16 %1, hh; }"
        : "=f"(f.x), "=f"(f.y) : "r"(h));
    return f;
}
static __device__ __forceinline__ uint32_t ex2h2(uint32_t a) {        // 2^x on both f16 halves
    uint32_t r;
    asm("ex2.approx.f16x2 %0, %1;" : "=r"(r) : "r"(a));
    return r;
}
static __device__ __forceinline__ uint32_t s2u(const void* p) {
    uint32_t a;
    asm("{ .reg .u64 t; cvta.to.shared.u64 t, %1; cvt.u32.u64 %0, t; }" : "=r"(a) : "l"(p));
    return a;
}
static __device__ __forceinline__ void ldsm4(uint32_t addr, uint32_t r[4]) {
    asm volatile("ldmatrix.sync.aligned.m8n8.x4.shared.b16 {%0,%1,%2,%3}, [%4];"
                 : "=r"(r[0]), "=r"(r[1]), "=r"(r[2]), "=r"(r[3]) : "r"(addr));
}
static __device__ __forceinline__ void ldsm4t(uint32_t addr, uint32_t r[4]) {
    asm volatile("ldmatrix.sync.aligned.m8n8.x4.trans.shared.b16 {%0,%1,%2,%3}, [%4];"
                 : "=r"(r[0]), "=r"(r[1]), "=r"(r[2]), "=r"(r[3]) : "r"(addr));
}
static __device__ __forceinline__ void mma16816(float d[4], const uint32_t a[4],
                                                uint32_t b0, uint32_t b1) {
    asm volatile("mma.sync.aligned.m16n8k16.row.col.f32.f16.f16.f32 "
                 "{%0,%1,%2,%3}, {%4,%5,%6,%7}, {%8,%9}, {%0,%1,%2,%3};"
                 : "+f"(d[0]), "+f"(d[1]), "+f"(d[2]), "+f"(d[3])
                 : "r"(a[0]), "r"(a[1]), "r"(a[2]), "r"(a[3]), "r"(b0), "r"(b1));
}

__global__ __launch_bounds__(NT, 2)
void diffattn_h4(const float* __restrict__ gq1, const float* __restrict__ gk1,
                 const float* __restrict__ gv,  const float* __restrict__ gq2,
                 const float* __restrict__ gk2, const float* __restrict__ glam,
                 float* __restrict__ gout)
{
    extern __shared__ __align__(1024) char smc[];
    const uint32_t sb = s2u(smc);
    const int t = threadIdx.x, wid = t >> 5, lane = t & 31;

    const int idx = blockIdx.x;
    const int a   = idx & 1;                  // 0: attn1, 1: attn2
    const int rst = idx >> 1;
    const int qt  = (NQT - 1) - (rst / BHN);  // heavy Q-tiles first
    const int bh  = rst % BHN;
    const int q0  = qt * BM;
    const size_t base = (size_t)bh * (size_t)(SEQ * Dh);
    const int nkt = 2 * qt + 2;

    const float* gq = a ? gq2 : gq1;
    const float* gk = a ? gk2 : gk1;

    const int rb = wid * 16;                  // warp's 16 Q rows

    // per-lane ldmatrix constants
    const int lr = lane & 7;
    const int lA = lr + ((lane >> 3) & 1) * 8;
    const int hA = (lane >> 4) & 1;
    const int cB = lane >> 3;

    // row/chunk for the fill loops
    const int frow = t >> 4, fch = t & 15;

    // ---- load Q (f16, pre-scaled by 1/sqrt(d)*log2e) ----
    #pragma unroll 2
    for (int it = 0; it < 8; ++it) {
        int fl = it * NT + t;
        int row = fl >> 4, ch = fl & 15;
        const float4* p = (const float4*)(gq + base + (size_t)(q0 + row) * Dh + ch * 8);
        float4 f0 = p[0], f1 = p[1];
        f0.x *= QSCALE_LOG2E; f0.y *= QSCALE_LOG2E; f0.z *= QSCALE_LOG2E; f0.w *= QSCALE_LOG2E;
        f1.x *= QSCALE_LOG2E; f1.y *= QSCALE_LOG2E; f1.z *= QSCALE_LOG2E; f1.w *= QSCALE_LOG2E;
        uint32_t sa = (uint32_t)(row * 256 + ((ch ^ (row & 7)) << 4));
        *(uint4*)(smc + O_QH + sa) = make_uint4(pk2h(f0.x, f0.y), pk2h(f0.z, f0.w),
                                                pk2h(f1.x, f1.y), pk2h(f1.z, f1.w));
    }

    // ---- fill K/V for tile 0 into buffer 0 ----
    {
        size_t goff = base + (size_t)(frow * 4) * Dh + fch * 8;
        #pragma unroll
        for (int rr = 0; rr < 4; ++rr) {
            const float4* pk = (const float4*)(gk + goff + (size_t)rr * Dh);
            const float4* pv = (const float4*)(gv + goff + (size_t)rr * Dh);
            float4 f0 = pk[0], f1 = pk[1];
            int row = frow * 4 + rr;
            uint32_t sa = (uint32_t)((row * 256) + ((fch ^ (row & 7)) << 4));
            *(uint4*)(smc + O_K0 + sa) = make_uint4(pk2h(f0.x, f0.y), pk2h(f0.z, f0.w),
                                                    pk2h(f1.x, f1.y), pk2h(f1.z, f1.w));
            float4 v0 = pv[0], v1 = pv[1];
            *(uint4*)(smc + O_V0 + sa) = make_uint4(pk2h(v0.x, v0.y), pk2h(v0.z, v0.w),
                                                    pk2h(v1.x, v1.y), pk2h(v1.z, v1.w));
        }
    }

    // accumulators + softmax state
    float o[16][4];
    #pragma unroll
    for (int nt = 0; nt < 16; ++nt)
        #pragma unroll
        for (int c = 0; c < 4; ++c) o[nt][c] = 0.0f;
    float l4[4] = {0.0f, 0.0f, 0.0f, 0.0f};   // row sums via ones-mma
    float mb[2] = {0.0f, 0.0f};

    const uint32_t aRowH = sb + O_QH + (uint32_t)((rb + lA) * 256);
    const uint32_t ONE2 = 0x3C003C00u;        // f16x2 {1.0, 1.0}
    const int rw0 = q0 + rb + (lane >> 2);

    __syncthreads();

    for (int kt = 0; kt < nkt; ++kt) {
        const int p = kt & 1;
        const uint32_t koff = p ? O_K1 : O_K0;
        const uint32_t voff = p ? O_V1 : O_V0;

        // ---- QK: S = Q * K (log2-units) ----
        float s[8][4];
        #pragma unroll
        for (int nt = 0; nt < 8; ++nt)
            #pragma unroll
            for (int c = 0; c < 4; ++c) s[nt][c] = 0.0f;

        #pragma unroll
        for (int kc2 = 0; kc2 < 4; ++kc2) {
            uint32_t ah[2][4];
            #pragma unroll
            for (int sc = 0; sc < 2; ++sc)
                ldsm4(aRowH + (uint32_t)(((2 * (2 * kc2 + sc) + hA) ^ lr) << 4), ah[sc]);
            uint32_t kb = sb + koff + (uint32_t)(lr * 256) +
                          (uint32_t)((((4 * kc2 + cB) ^ lr) << 4));
            #pragma unroll
            for (int nt = 0; nt < 8; ++nt) {
                uint32_t b[4];
                ldsm4(kb + (uint32_t)(nt * 2048), b);
                mma16816(s[nt], ah[0], b[0], b[1]);
                mma16816(s[nt], ah[1], b[2], b[3]);
            }
        }

        // ---- fill next K/V tile into the other buffer (LDGs land during softmax/PV) ----
        if (kt + 1 < nkt) {
            const uint32_t nk = p ? O_K0 : O_K1;
            const uint32_t nv = p ? O_V0 : O_V1;
            size_t goff = base + (size_t)((kt + 1) * BN + frow * 4) * Dh + fch * 8;
            #pragma unroll
            for (int rr = 0; rr < 4; ++rr) {
                const float4* pk = (const float4*)(gk + goff + (size_t)rr * Dh);
                const float4* pv = (const float4*)(gv + goff + (size_t)rr * Dh);
                float4 f0 = pk[0], f1 = pk[1];
                int row = frow * 4 + rr;
                uint32_t sa = (uint32_t)((row * 256) + ((fch ^ (row & 7)) << 4));
                *(uint4*)(smc + nk + sa) = make_uint4(pk2h(f0.x, f0.y), pk2h(f0.z, f0.w),
                                                      pk2h(f1.x, f1.y), pk2h(f1.z, f1.w));
                float4 v0 = pv[0], v1 = pv[1];
                *(uint4*)(smc + nv + sa) = make_uint4(pk2h(v0.x, v0.y), pk2h(v0.z, v0.w),
                                                      pk2h(v1.x, v1.y), pk2h(v1.z, v1.w));
            }
        }

        // ---- causal mask (diagonal 128-block only) ----
        if (kt >= 2 * qt) {
            const int colb = kt * 64 + ((lane & 3) << 1);
            #pragma unroll
            for (int nt = 0; nt < 8; ++nt)
                #pragma unroll
                for (int c = 0; c < 4; ++c) {
                    int col = colb + nt * 8 + (c & 1);
                    int rw  = rw0 + 8 * (c >> 1);
                    if (col > rw) s[nt][c] = -CUDART_INF_F;
                }
        }

        // ---- fixed softmax base from tile 0 ----
        if (kt == 0) {
            #pragma unroll
            for (int h = 0; h < 2; ++h) {
                float m = -CUDART_INF_F;
                #pragma unroll
                for (int nt = 0; nt < 8; ++nt) {
                    m = fmaxf(m, s[nt][2 * h]);
                    m = fmaxf(m, s[nt][2 * h + 1]);
                }
                m = fmaxf(m, __shfl_xor_sync(0xffffffffu, m, 1));
                m = fmaxf(m, __shfl_xor_sync(0xffffffffu, m, 2));
                mb[h] = m;
            }
        }

        // ---- softmax chunk -> l-mma + PV mmas ----
        #pragma unroll
        for (int kc = 0; kc < 4; ++kc) {
            uint32_t ph[4];
            #pragma unroll
            for (int q2 = 0; q2 < 2; ++q2) {
                const int nt = 2 * kc + q2;
                ph[2 * q2]     = ex2h2(pk2h(s[nt][0] - mb[0], s[nt][1] - mb[0]));
                ph[2 * q2 + 1] = ex2h2(pk2h(s[nt][2] - mb[1], s[nt][3] - mb[1]));
            }
            mma16816(l4, ph, ONE2, ONE2);
            uint32_t vrow = sb + voff + (uint32_t)((16 * kc + lA) * 256);
            #pragma unroll
            for (int nt2 = 0; nt2 < 8; ++nt2) {
                uint32_t b[4];
                ldsm4t(vrow + (uint32_t)((((2 * nt2 + hA) ^ lr) << 4)), b);
                mma16816(o[2 * nt2],     ph, b[0], b[1]);
                mma16816(o[2 * nt2 + 1], ph, b[2], b[3]);
            }
        }

        __syncthreads();   // fill(kt+1) complete; buffer p free for next fill
    }

    // ---- epilogue: attn1 -> gout (A1/l, f32), attn2 -> g_a2h (lam*A2/l, f16x2) ----
    if (a == 0) {
        const float i0 = 1.0f / l4[0];
        const float i1 = 1.0f / l4[2];
        #pragma unroll
        for (int nt = 0; nt < 16; ++nt) {
            const int d0 = nt * 8 + ((lane & 3) << 1);
            float2 w;
            w.x = o[nt][0] * i0; w.y = o[nt][1] * i0;
            *(float2*)(gout + base + (size_t)rw0 * Dh + d0) = w;
            w.x = o[nt][2] * i1; w.y = o[nt][3] * i1;
            *(float2*)(gout + base + (size_t)(rw0 + 8) * Dh + d0) = w;
        }
    } else {
        const float sc = __expf(glam[0]);
        const float i0 = sc / l4[0];
        const float i1 = sc / l4[2];
        uint32_t* dst = g_a2h;
        #pragma unroll
        for (int nt = 0; nt < 16; ++nt) {
            const int d0 = nt * 8 + ((lane & 3) << 1);
            dst[(base + (size_t)rw0 * Dh + d0) >> 1]       = pk2h(o[nt][0] * i0, o[nt][1] * i0);
            dst[(base + (size_t)(rw0 + 8) * Dh + d0) >> 1] = pk2h(o[nt][2] * i1, o[nt][3] * i1);
        }
    }
}

__global__ __launch_bounds__(256, 8)
void diff_combine2(float* __restrict__ out)
{
    // 2 x float4 (and matching 1 x uint4 of f16x2) per thread
    int i = blockIdx.x * 256 + threadIdx.x;          // uint4 index into g_a2h
    uint4 bh = ((const uint4*)g_a2h)[i];
    float4* po = (float4*)out + i * 2;
    float4 o0 = po[0], o1 = po[1];
    float2 u;
    u = up2h(bh.x); o0.x -= u.x; o0.y -= u.y;
    u = up2h(bh.y); o0.z -= u.x; o0.w -= u.y;
    u = up2h(bh.z); o1.x -= u.x; o1.y -= u.y;
    u = up2h(bh.w); o1.z -= u.x; o1.w -= u.y;
    po[0] = o0; po[1] = o1;
}

extern "C" void kernel_launch(void* const* d_in, const int* in_sizes, int n_in,
                              void* d_out, int out_size)
{
    (void)in_sizes; (void)n_in; (void)out_size;
    const float* q1  = (const float*)d_in[0];
    const float* k1  = (const float*)d_in[1];
    const float* v   = (const float*)d_in[2];
    const float* q2  = (const float*)d_in[3];
    const float* k2  = (const float*)d_in[4];
    const float* lam = (const float*)d_in[5];

    cudaFuncSetAttribute(diffattn_h4, cudaFuncAttributeMaxDynamicSharedMemorySize, SM_TOTAL);
    diffattn_h4<<<2 * NQT * BHN, NT, SM_TOTAL>>>(q1, k1, v, q2, k2, lam, (float*)d_out);
    diff_combine2<<<NOUT / 8 / 256, 256>>>((float*)d_out);
}